// round 2
// baseline (speedup 1.0000x reference)
#include <cuda_runtime.h>
#include <math.h>
#include <stdint.h>

// ---------------------------------------------------------------------------
// Trellis2 windowed 3D attention, fp32 (double-buffered SGEMM).
//   x[32768,1024] -> qkv gemm -> rmsnorm+rope -> windowed attn (8^3) -> out gemm
// ---------------------------------------------------------------------------

#define R3 32
#define WINSZ 8
#define NH 16
#define CH 1024
#define HD 64
#define NTOK (R3*R3*R3)      // 32768
#define NWIN 64              // (32/8)^3
#define WTOK 512             // 8^3

// ---- scratch (static device arrays; allocation-free at launch time) ----
__device__ float g_qkv[(size_t)NTOK * 3 * CH];            // 402 MB
__device__ float g_qw [(size_t)NWIN * NH * WTOK * HD];    // 134 MB  [w][h][p][d]
__device__ float g_kw [(size_t)NWIN * NH * WTOK * HD];
__device__ float g_vw [(size_t)NWIN * NH * WTOK * HD];
__device__ float g_hbuf[(size_t)NTOK * CH];               // attn out, token layout

// ---------------------------------------------------------------------------
// SGEMM: C[M,N] = A[M,K] @ B[K,N] + bias[N]
// 128x128 tile, BK=8, 256 threads, 8x8/thread, double-buffered smem,
// global prefetch overlapped with compute. M%128==0, N%128==0, K%8==0.
// ---------------------------------------------------------------------------
__global__ __launch_bounds__(256) void sgemm_bias(
    const float* __restrict__ A, const float* __restrict__ B,
    const float* __restrict__ bias, float* __restrict__ Cm,
    int M, int Nn, int K)
{
    __shared__ float As[2][8][128];
    __shared__ float Bs[2][8][128];
    const int tid = threadIdx.x;
    const int bx = blockIdx.x;   // N tiles
    const int by = blockIdx.y;   // M tiles
    const int tx = tid & 15;
    const int ty = tid >> 4;

    const float* Ab = A + (size_t)by * 128 * K;
    const float* Bb = B + bx * 128;

    float acc[8][8];
#pragma unroll
    for (int i = 0; i < 8; i++)
#pragma unroll
        for (int j = 0; j < 8; j++) acc[i][j] = 0.f;

    const int arow = tid >> 1, acol = (tid & 1) * 4;
    const int brow = tid >> 5, bcol = (tid & 31) * 4;

    // preload tile 0
    float4 av = *(const float4*)(Ab + (size_t)arow * K + acol);
    float4 bv = *(const float4*)(Bb + (size_t)brow * Nn + bcol);
    int c = 0;
    As[c][acol + 0][arow] = av.x;
    As[c][acol + 1][arow] = av.y;
    As[c][acol + 2][arow] = av.z;
    As[c][acol + 3][arow] = av.w;
    *(float4*)&Bs[c][brow][bcol] = bv;
    __syncthreads();

    for (int k0 = 8; k0 <= K; k0 += 8) {
        const bool has_next = (k0 < K);
        if (has_next) {
            av = *(const float4*)(Ab + (size_t)arow * K + k0 + acol);
            bv = *(const float4*)(Bb + (size_t)(k0 + brow) * Nn + bcol);
        }
#pragma unroll
        for (int kk = 0; kk < 8; kk++) {
            float a[8], b[8];
            *(float4*)&a[0] = *(float4*)&As[c][kk][ty * 8];
            *(float4*)&a[4] = *(float4*)&As[c][kk][ty * 8 + 4];
            *(float4*)&b[0] = *(float4*)&Bs[c][kk][tx * 8];
            *(float4*)&b[4] = *(float4*)&Bs[c][kk][tx * 8 + 4];
#pragma unroll
            for (int i = 0; i < 8; i++)
#pragma unroll
                for (int j = 0; j < 8; j++)
                    acc[i][j] += a[i] * b[j];
        }
        if (has_next) {
            const int n = c ^ 1;
            As[n][acol + 0][arow] = av.x;
            As[n][acol + 1][arow] = av.y;
            As[n][acol + 2][arow] = av.z;
            As[n][acol + 3][arow] = av.w;
            *(float4*)&Bs[n][brow][bcol] = bv;
            __syncthreads();
            c = n;
        }
    }

#pragma unroll
    for (int i = 0; i < 8; i++) {
        size_t row = (size_t)by * 128 + ty * 8 + i;
        float* crow = Cm + row * Nn + bx * 128 + tx * 8;
        const float* brw = bias + bx * 128 + tx * 8;
#pragma unroll
        for (int j = 0; j < 8; j += 4) {
            float4 v;
            v.x = acc[i][j + 0] + brw[j + 0];
            v.y = acc[i][j + 1] + brw[j + 1];
            v.z = acc[i][j + 2] + brw[j + 2];
            v.w = acc[i][j + 3] + brw[j + 3];
            *(float4*)(crow + j) = v;
        }
    }
}

// ---------------------------------------------------------------------------
// Post-process: per (token, head) RMSNorm + RoPE on q,k; scatter q,k,v into
// windowed layout [w][h][p][d]. One block per token, 16 warps = 16 heads.
// Each lane holds one (even,odd) pair: d = 2*lane, 2*lane+1.
// ---------------------------------------------------------------------------
__global__ __launch_bounds__(512) void qkv_post(
    const int* __restrict__ coords,
    const float* __restrict__ gamma_q,
    const float* __restrict__ gamma_k)
{
    const int n = blockIdx.x;
    const int h = threadIdx.x >> 5;
    const int lane = threadIdx.x & 31;

    const int x = n >> 10, y = (n >> 5) & 31, z = n & 31;
    const int w = ((x >> 3) * 4 + (y >> 3)) * 4 + (z >> 3);
    const int p = ((x & 7) * 8 + (y & 7)) * 8 + (z & 7);

    // RoPE phase for pair index j = lane (j<30: c=j/10, f=j%10; else identity)
    float cosp = 1.f, sinp = 0.f;
    if (lane < 30) {
        const int c = lane / 10, f = lane % 10;
        // freq = 10000^(-f/10) = exp(-f * ln(10000)/10)
        const float freq = expf(-(float)f * 0.9210340371976183f);
        const float phase = (float)coords[n * 3 + c] * freq;
        sincosf(phase, &sinp, &cosp);
    }

    const size_t base  = (size_t)n * (3 * CH);
    const size_t wbase = (((size_t)w * NH + h) * WTOK + p) * HD;

    // Q
    {
        float2 t = *(const float2*)&g_qkv[base + h * HD + 2 * lane];
        float ss = t.x * t.x + t.y * t.y;
#pragma unroll
        for (int off = 16; off > 0; off >>= 1)
            ss += __shfl_xor_sync(0xffffffffu, ss, off);
        const float inv = 8.0f / fmaxf(sqrtf(ss), 1e-12f);
        float2 g = *(const float2*)&gamma_q[h * HD + 2 * lane];
        const float t0 = t.x * inv * g.x;
        const float t1 = t.y * inv * g.y;
        float2 o;
        o.x = t0 * cosp - t1 * sinp;
        o.y = t0 * sinp + t1 * cosp;
        *(float2*)&g_qw[wbase + 2 * lane] = o;
    }
    // K
    {
        float2 t = *(const float2*)&g_qkv[base + CH + h * HD + 2 * lane];
        float ss = t.x * t.x + t.y * t.y;
#pragma unroll
        for (int off = 16; off > 0; off >>= 1)
            ss += __shfl_xor_sync(0xffffffffu, ss, off);
        const float inv = 8.0f / fmaxf(sqrtf(ss), 1e-12f);
        float2 g = *(const float2*)&gamma_k[h * HD + 2 * lane];
        const float t0 = t.x * inv * g.x;
        const float t1 = t.y * inv * g.y;
        float2 o;
        o.x = t0 * cosp - t1 * sinp;
        o.y = t0 * sinp + t1 * cosp;
        *(float2*)&g_kw[wbase + 2 * lane] = o;
    }
    // V (plain copy into windowed layout)
    {
        float2 t = *(const float2*)&g_qkv[base + 2 * CH + h * HD + 2 * lane];
        *(float2*)&g_vw[wbase + 2 * lane] = t;
    }
}

// ---------------------------------------------------------------------------
// Windowed attention. grid = (16 q-tiles, 16 heads, 64 windows), 128 threads.
// Per block: 32 q rows x 512 keys, D=64. Two-pass softmax with scores held
// transposed in smem. Dynamic smem ~98 KB.
// smem layout (floats):
//   sQt [64][36]  (Q^T:  [d][r], scaled by 1/8)
//   sKV [64][68]  (K^T [d][k] for pass 1; V [k][d] for pass 2)
//   sS  [512][36] (scores transposed: [c][r])
//   sSum[32]      (1/rowsum)
// ---------------------------------------------------------------------------
#define SM_QT 0
#define SM_KV (64 * 36)
#define SM_S  (SM_KV + 64 * 68)
#define SM_SUM (SM_S + 512 * 36)
#define ATTN_SMEM_FLOATS (SM_SUM + 32)

__global__ __launch_bounds__(128) void attn_win()
{
    extern __shared__ float sm[];
    float* sQt  = sm + SM_QT;
    float* sKV  = sm + SM_KV;
    float* sS   = sm + SM_S;
    float* sSum = sm + SM_SUM;

    const int tid = threadIdx.x;
    const int qt = blockIdx.x, h = blockIdx.y, w = blockIdx.z;
    const int ty = tid >> 4;   // 0..7  (4 q rows each)
    const int tx = tid & 15;   // 0..15 (4 cols each)

    const float* Qg = g_qw + (((size_t)w * NH + h) * WTOK + qt * 32) * HD;
    const float* Kg = g_kw + ((size_t)w * NH + h) * WTOK * HD;
    const float* Vg = g_vw + ((size_t)w * NH + h) * WTOK * HD;

    // load Q transposed, pre-scaled by 1/sqrt(D)=0.125
#pragma unroll
    for (int t = 0; t < 4; t++) {
        const int idx = t * 128 + tid;        // 0..511
        const int r = idx >> 4;               // 0..31
        const int d4 = (idx & 15) * 4;
        float4 v = *(const float4*)(Qg + (size_t)r * HD + d4);
        sQt[(d4 + 0) * 36 + r] = v.x * 0.125f;
        sQt[(d4 + 1) * 36 + r] = v.y * 0.125f;
        sQt[(d4 + 2) * 36 + r] = v.z * 0.125f;
        sQt[(d4 + 3) * 36 + r] = v.w * 0.125f;
    }

    // ---- pass 1: scores S[r][c] = (Q/8) . K ----
    for (int kt = 0; kt < 8; kt++) {
        __syncthreads();   // prior tile consumed (and Q load visible on kt=0)
#pragma unroll
        for (int t = 0; t < 8; t++) {
            const int idx = t * 128 + tid;    // 0..1023
            const int k = idx >> 4;
            const int d4 = (idx & 15) * 4;
            float4 v = *(const float4*)(Kg + (size_t)(kt * 64 + k) * HD + d4);
            sKV[(d4 + 0) * 68 + k] = v.x;
            sKV[(d4 + 1) * 68 + k] = v.y;
            sKV[(d4 + 2) * 68 + k] = v.z;
            sKV[(d4 + 3) * 68 + k] = v.w;
        }
        __syncthreads();

        float acc[4][4];
#pragma unroll
        for (int i = 0; i < 4; i++)
#pragma unroll
            for (int j = 0; j < 4; j++) acc[i][j] = 0.f;

#pragma unroll
        for (int d = 0; d < 64; d++) {
            float a[4], b[4];
            *(float4*)a = *(float4*)&sQt[d * 36 + ty * 4];
            *(float4*)b = *(float4*)&sKV[d * 68 + tx * 4];
#pragma unroll
            for (int i = 0; i < 4; i++)
#pragma unroll
                for (int j = 0; j < 4; j++)
                    acc[i][j] += a[i] * b[j];
        }
        // store transposed: sS[c][r]
#pragma unroll
        for (int j = 0; j < 4; j++)
#pragma unroll
            for (int i = 0; i < 4; i++)
                sS[(kt * 64 + tx * 4 + j) * 36 + ty * 4 + i] = acc[i][j];
    }
    __syncthreads();

    // ---- softmax over c (512), rows split across 4 warps ----
    {
        const int warp = tid >> 5, lane = tid & 31;
#pragma unroll
        for (int rr = 0; rr < 8; rr++) {
            const int r = warp * 8 + rr;
            float mx = -1e30f;
            for (int c = lane; c < 512; c += 32)
                mx = fmaxf(mx, sS[c * 36 + r]);
#pragma unroll
            for (int off = 16; off > 0; off >>= 1)
                mx = fmaxf(mx, __shfl_xor_sync(0xffffffffu, mx, off));
            float sum = 0.f;
            for (int c = lane; c < 512; c += 32) {
                const float e = __expf(sS[c * 36 + r] - mx);
                sS[c * 36 + r] = e;
                sum += e;
            }
#pragma unroll
            for (int off = 16; off > 0; off >>= 1)
                sum += __shfl_xor_sync(0xffffffffu, sum, off);
            if (lane == 0) sSum[r] = 1.0f / sum;
        }
    }
    __syncthreads();

    // ---- pass 2: O = P @ V ----
    float o[4][4];
#pragma unroll
    for (int i = 0; i < 4; i++)
#pragma unroll
        for (int j = 0; j < 4; j++) o[i][j] = 0.f;

    for (int kt = 0; kt < 8; kt++) {
#pragma unroll
        for (int t = 0; t < 8; t++) {
            const int idx = t * 128 + tid;
            const int k = idx >> 4;
            const int d4 = (idx & 15) * 4;
            *(float4*)&sKV[k * 68 + d4] =
                *(const float4*)(Vg + (size_t)(kt * 64 + k) * HD + d4);
        }
        __syncthreads();
#pragma unroll
        for (int c = 0; c < 64; c++) {
            float a[4], b[4];
            *(float4*)a = *(float4*)&sS[(kt * 64 + c) * 36 + ty * 4];
            *(float4*)b = *(float4*)&sKV[c * 68 + tx * 4];
#pragma unroll
            for (int i = 0; i < 4; i++)
#pragma unroll
                for (int j = 0; j < 4; j++)
                    o[i][j] += a[i] * b[j];
        }
        __syncthreads();   // before overwriting sKV
    }

    // ---- write O back to natural token layout ----
    const int wx = w >> 4, wy = (w >> 2) & 3, wz = w & 3;
#pragma unroll
    for (int i = 0; i < 4; i++) {
        const int r = ty * 4 + i;
        const int p = qt * 32 + r;
        const int ix = p >> 6, iy = (p >> 3) & 7, iz = p & 7;
        const int n = ((wx * 8 + ix) * 32 + (wy * 8 + iy)) * 32 + (wz * 8 + iz);
        const float s = sSum[r];
        float4 v;
        v.x = o[i][0] * s;
        v.y = o[i][1] * s;
        v.z = o[i][2] * s;
        v.w = o[i][3] * s;
        *(float4*)&g_hbuf[(size_t)n * CH + h * HD + tx * 4] = v;
    }
}

// ---------------------------------------------------------------------------
// kernel_launch
// inputs: 0:x 1:coords 2:Wqkv 3:bqkv 4:gamma_q 5:gamma_k 6:Wout 7:bout
// ---------------------------------------------------------------------------
extern "C" void kernel_launch(void* const* d_in, const int* in_sizes, int n_in,
                              void* d_out, int out_size)
{
    const float* x       = (const float*)d_in[0];
    const int*   coords  = (const int*)  d_in[1];
    const float* Wqkv    = (const float*)d_in[2];
    const float* bqkv    = (const float*)d_in[3];
    const float* gamma_q = (const float*)d_in[4];
    const float* gamma_k = (const float*)d_in[5];
    const float* Wout    = (const float*)d_in[6];
    const float* bout    = (const float*)d_in[7];
    float* out = (float*)d_out;

    float *qkv_p, *h_p;
    cudaGetSymbolAddress((void**)&qkv_p, g_qkv);
    cudaGetSymbolAddress((void**)&h_p,  g_hbuf);

    // 1) qkv = x @ Wqkv + bqkv           [32768,3072]
    sgemm_bias<<<dim3(3 * CH / 128, NTOK / 128), 256>>>(
        x, Wqkv, bqkv, qkv_p, NTOK, 3 * CH, CH);

    // 2) rmsnorm + rope + window scatter
    qkv_post<<<NTOK, 512>>>(coords, gamma_q, gamma_k);

    // 3) windowed attention
    const int smem_bytes = ATTN_SMEM_FLOATS * sizeof(float);
    cudaFuncSetAttribute(attn_win, cudaFuncAttributeMaxDynamicSharedMemorySize,
                         smem_bytes);
    attn_win<<<dim3(16, NH, NWIN), 128, smem_bytes>>>();

    // 4) out = h @ Wout + bout           [32768,1024]
    sgemm_bias<<<dim3(CH / 128, NTOK / 128), 256>>>(
        h_p, Wout, bout, out, NTOK, CH, CH);
}

// round 4
// speedup vs baseline: 1.7560x; 1.7560x over previous
#include <cuda_runtime.h>
#include <math.h>
#include <stdint.h>

// ---------------------------------------------------------------------------
// Trellis2 windowed 3D attention.
//   x[32768,1024] -> qkv gemm (TF32 mma) -> rmsnorm+rope -> windowed attn (fp32)
//   -> out gemm (TF32 mma)
// ---------------------------------------------------------------------------

#define R3 32
#define NH 16
#define CH 1024
#define HD 64
#define NTOK (R3*R3*R3)      // 32768
#define NWIN 64              // (32/8)^3
#define WTOK 512             // 8^3

// ---- scratch (static device arrays; allocation-free at launch time) ----
__device__ float g_qkv[(size_t)NTOK * 3 * CH];            // 402 MB
__device__ float g_qw [(size_t)NWIN * NH * WTOK * HD];    // 134 MB  [w][h][p][d]
__device__ float g_kw [(size_t)NWIN * NH * WTOK * HD];
__device__ float g_vw [(size_t)NWIN * NH * WTOK * HD];
__device__ float g_hbuf[(size_t)NTOK * CH];               // attn out, token layout

// ---------------------------------------------------------------------------
// TF32 tensor-core GEMM: C[M,N] = A[M,K] @ B[K,N] + bias[N]
// 128x128 block tile, BK=16, 256 threads (8 warps), warp tile 64x32.
// mma.sync m16n8k8 tf32. Double-buffered smem. M%128==0, N%128==0, K%16==0.
// Smem pitches chosen so all fragment LDS are bank-conflict-free:
//   As[m][20]: bank = (20m+k)%32 distinct over the quad access pattern
//   Bs[k][136]: bank = (8k+n)%32 distinct over k%4 x n%8
// ---------------------------------------------------------------------------
__device__ __forceinline__ unsigned f2tf32(float f) {
    unsigned u;
    asm("cvt.rna.tf32.f32 %0, %1;" : "=r"(u) : "f"(f));
    return u;
}

__device__ __forceinline__ void mma1688(float d[4], const unsigned a[4],
                                        const unsigned b[2]) {
    asm volatile(
        "mma.sync.aligned.m16n8k8.row.col.f32.tf32.tf32.f32 "
        "{%0,%1,%2,%3}, {%4,%5,%6,%7}, {%8,%9}, {%0,%1,%2,%3};"
        : "+f"(d[0]), "+f"(d[1]), "+f"(d[2]), "+f"(d[3])
        : "r"(a[0]), "r"(a[1]), "r"(a[2]), "r"(a[3]), "r"(b[0]), "r"(b[1]));
}

__global__ __launch_bounds__(256) void sgemm_tf32(
    const float* __restrict__ A, const float* __restrict__ B,
    const float* __restrict__ bias, float* __restrict__ Cm,
    int M, int Nn, int K)
{
    __shared__ unsigned As[2][128][20];   // [buf][m][k] tf32 bits
    __shared__ unsigned Bs[2][16][136];   // [buf][k][n]

    const int tid  = threadIdx.x;
    const int warp = tid >> 5, lane = tid & 31;
    const int wm = warp >> 2;          // 0..1  (64-row half)
    const int wn = warp & 3;           // 0..3  (32-col quarter)
    const int grp = lane >> 2, tg = lane & 3;
    const int bx = blockIdx.x, by = blockIdx.y;

    const float* Ab = A + (size_t)by * 128 * K;
    const float* Bb = B + bx * 128;

    // loader mapping
    const int am  = tid >> 2;          // A row (this thread: am and am+64)
    const int ac4 = (tid & 3) * 4;     // A col within BK tile
    const int bk  = tid >> 5;          // B row (this thread: bk and bk+8)
    const int bn4 = (lane) * 4;        // B col (float4)

    float d[4][4][4];
#pragma unroll
    for (int mt = 0; mt < 4; mt++)
#pragma unroll
        for (int nt = 0; nt < 4; nt++)
#pragma unroll
            for (int j = 0; j < 4; j++) d[mt][nt][j] = 0.f;

    // ---- preload tile 0 ----
    {
        float4 a0 = *(const float4*)(Ab + (size_t)am        * K + ac4);
        float4 a1 = *(const float4*)(Ab + (size_t)(am + 64) * K + ac4);
        float4 b0 = *(const float4*)(Bb + (size_t)bk       * Nn + bn4);
        float4 b1 = *(const float4*)(Bb + (size_t)(bk + 8) * Nn + bn4);
        uint4 u;
        u.x = f2tf32(a0.x); u.y = f2tf32(a0.y); u.z = f2tf32(a0.z); u.w = f2tf32(a0.w);
        *(uint4*)&As[0][am][ac4] = u;
        u.x = f2tf32(a1.x); u.y = f2tf32(a1.y); u.z = f2tf32(a1.z); u.w = f2tf32(a1.w);
        *(uint4*)&As[0][am + 64][ac4] = u;
        u.x = f2tf32(b0.x); u.y = f2tf32(b0.y); u.z = f2tf32(b0.z); u.w = f2tf32(b0.w);
        *(uint4*)&Bs[0][bk][bn4] = u;
        u.x = f2tf32(b1.x); u.y = f2tf32(b1.y); u.z = f2tf32(b1.z); u.w = f2tf32(b1.w);
        *(uint4*)&Bs[0][bk + 8][bn4] = u;
    }
    __syncthreads();

    int buf = 0;
    for (int k0 = 16; k0 <= K; k0 += 16) {
        const bool has_next = (k0 < K);
        float4 ra0, ra1, rb0, rb1;
        if (has_next) {
            ra0 = *(const float4*)(Ab + (size_t)am        * K + k0 + ac4);
            ra1 = *(const float4*)(Ab + (size_t)(am + 64) * K + k0 + ac4);
            rb0 = *(const float4*)(Bb + (size_t)(k0 + bk    ) * Nn + bn4);
            rb1 = *(const float4*)(Bb + (size_t)(k0 + bk + 8) * Nn + bn4);
        }

        // ---- compute on current buffer: two k8 steps ----
#pragma unroll
        for (int ks = 0; ks < 2; ks++) {
            const int kb = ks * 8;
            unsigned a[4][4], b[4][2];
#pragma unroll
            for (int mt = 0; mt < 4; mt++) {
                const int r = wm * 64 + mt * 16 + grp;
                a[mt][0] = As[buf][r    ][kb + tg];
                a[mt][1] = As[buf][r + 8][kb + tg];
                a[mt][2] = As[buf][r    ][kb + tg + 4];
                a[mt][3] = As[buf][r + 8][kb + tg + 4];
            }
#pragma unroll
            for (int nt = 0; nt < 4; nt++) {
                const int c = wn * 32 + nt * 8 + grp;
                b[nt][0] = Bs[buf][kb + tg    ][c];
                b[nt][1] = Bs[buf][kb + tg + 4][c];
            }
#pragma unroll
            for (int mt = 0; mt < 4; mt++)
#pragma unroll
                for (int nt = 0; nt < 4; nt++)
                    mma1688(d[mt][nt], a[mt], b[nt]);
        }

        if (has_next) {
            const int nb = buf ^ 1;
            uint4 u;
            u.x = f2tf32(ra0.x); u.y = f2tf32(ra0.y); u.z = f2tf32(ra0.z); u.w = f2tf32(ra0.w);
            *(uint4*)&As[nb][am][ac4] = u;
            u.x = f2tf32(ra1.x); u.y = f2tf32(ra1.y); u.z = f2tf32(ra1.z); u.w = f2tf32(ra1.w);
            *(uint4*)&As[nb][am + 64][ac4] = u;
            u.x = f2tf32(rb0.x); u.y = f2tf32(rb0.y); u.z = f2tf32(rb0.z); u.w = f2tf32(rb0.w);
            *(uint4*)&Bs[nb][bk][bn4] = u;
            u.x = f2tf32(rb1.x); u.y = f2tf32(rb1.y); u.z = f2tf32(rb1.z); u.w = f2tf32(rb1.w);
            *(uint4*)&Bs[nb][bk + 8][bn4] = u;
            __syncthreads();
            buf = nb;
        }
    }

    // ---- epilogue: add bias, write float2 pairs ----
#pragma unroll
    for (int mt = 0; mt < 4; mt++) {
#pragma unroll
        for (int nt = 0; nt < 4; nt++) {
            const int col = bx * 128 + wn * 32 + nt * 8 + 2 * tg;
            const float bx0 = bias[col], bx1 = bias[col + 1];
            const size_t r0 = (size_t)by * 128 + wm * 64 + mt * 16 + grp;
            float2 v0, v1;
            v0.x = d[mt][nt][0] + bx0; v0.y = d[mt][nt][1] + bx1;
            v1.x = d[mt][nt][2] + bx0; v1.y = d[mt][nt][3] + bx1;
            *(float2*)(Cm + r0 * Nn + col)       = v0;
            *(float2*)(Cm + (r0 + 8) * Nn + col) = v1;
        }
    }
}

// ---------------------------------------------------------------------------
// Post-process: per (token, head) RMSNorm + RoPE on q,k; scatter q,k,v into
// windowed layout [w][h][p][d]. One block per token, 16 warps = 16 heads.
// ---------------------------------------------------------------------------
__global__ __launch_bounds__(512) void qkv_post(
    const int* __restrict__ coords,
    const float* __restrict__ gamma_q,
    const float* __restrict__ gamma_k)
{
    const int n = blockIdx.x;
    const int h = threadIdx.x >> 5;
    const int lane = threadIdx.x & 31;

    const int x = n >> 10, y = (n >> 5) & 31, z = n & 31;
    const int w = ((x >> 3) * 4 + (y >> 3)) * 4 + (z >> 3);
    const int p = ((x & 7) * 8 + (y & 7)) * 8 + (z & 7);

    float cosp = 1.f, sinp = 0.f;
    if (lane < 30) {
        const int c = lane / 10, f = lane % 10;
        const float freq = expf(-(float)f * 0.9210340371976183f);
        const float phase = (float)coords[n * 3 + c] * freq;
        sincosf(phase, &sinp, &cosp);
    }

    const size_t base  = (size_t)n * (3 * CH);
    const size_t wbase = (((size_t)w * NH + h) * WTOK + p) * HD;

    // Q
    {
        float2 t = *(const float2*)&g_qkv[base + h * HD + 2 * lane];
        float ss = t.x * t.x + t.y * t.y;
#pragma unroll
        for (int off = 16; off > 0; off >>= 1)
            ss += __shfl_xor_sync(0xffffffffu, ss, off);
        const float inv = 8.0f / fmaxf(sqrtf(ss), 1e-12f);
        float2 g = *(const float2*)&gamma_q[h * HD + 2 * lane];
        const float t0 = t.x * inv * g.x;
        const float t1 = t.y * inv * g.y;
        float2 o;
        o.x = t0 * cosp - t1 * sinp;
        o.y = t0 * sinp + t1 * cosp;
        *(float2*)&g_qw[wbase + 2 * lane] = o;
    }
    // K
    {
        float2 t = *(const float2*)&g_qkv[base + CH + h * HD + 2 * lane];
        float ss = t.x * t.x + t.y * t.y;
#pragma unroll
        for (int off = 16; off > 0; off >>= 1)
            ss += __shfl_xor_sync(0xffffffffu, ss, off);
        const float inv = 8.0f / fmaxf(sqrtf(ss), 1e-12f);
        float2 g = *(const float2*)&gamma_k[h * HD + 2 * lane];
        const float t0 = t.x * inv * g.x;
        const float t1 = t.y * inv * g.y;
        float2 o;
        o.x = t0 * cosp - t1 * sinp;
        o.y = t0 * sinp + t1 * cosp;
        *(float2*)&g_kw[wbase + 2 * lane] = o;
    }
    // V
    {
        float2 t = *(const float2*)&g_qkv[base + 2 * CH + h * HD + 2 * lane];
        *(float2*)&g_vw[wbase + 2 * lane] = t;
    }
}

// ---------------------------------------------------------------------------
// Windowed attention (fp32). grid = (16 q-tiles, 16 heads, 64 windows),
// 128 threads. 32 q rows x 512 keys, D=64. ~98 KB dynamic smem.
// ---------------------------------------------------------------------------
#define SM_QT 0
#define SM_KV (64 * 36)
#define SM_S  (SM_KV + 64 * 68)
#define SM_SUM (SM_S + 512 * 36)
#define ATTN_SMEM_FLOATS (SM_SUM + 32)

__global__ __launch_bounds__(128) void attn_win()
{
    extern __shared__ float sm[];
    float* sQt  = sm + SM_QT;
    float* sKV  = sm + SM_KV;
    float* sS   = sm + SM_S;
    float* sSum = sm + SM_SUM;

    const int tid = threadIdx.x;
    const int qt = blockIdx.x, h = blockIdx.y, w = blockIdx.z;
    const int ty = tid >> 4;
    const int tx = tid & 15;

    const float* Qg = g_qw + (((size_t)w * NH + h) * WTOK + qt * 32) * HD;
    const float* Kg = g_kw + ((size_t)w * NH + h) * WTOK * HD;
    const float* Vg = g_vw + ((size_t)w * NH + h) * WTOK * HD;

#pragma unroll
    for (int t = 0; t < 4; t++) {
        const int idx = t * 128 + tid;
        const int r = idx >> 4;
        const int d4 = (idx & 15) * 4;
        float4 v = *(const float4*)(Qg + (size_t)r * HD + d4);
        sQt[(d4 + 0) * 36 + r] = v.x * 0.125f;
        sQt[(d4 + 1) * 36 + r] = v.y * 0.125f;
        sQt[(d4 + 2) * 36 + r] = v.z * 0.125f;
        sQt[(d4 + 3) * 36 + r] = v.w * 0.125f;
    }

    for (int kt = 0; kt < 8; kt++) {
        __syncthreads();
#pragma unroll
        for (int t = 0; t < 8; t++) {
            const int idx = t * 128 + tid;
            const int k = idx >> 4;
            const int d4 = (idx & 15) * 4;
            float4 v = *(const float4*)(Kg + (size_t)(kt * 64 + k) * HD + d4);
            sKV[(d4 + 0) * 68 + k] = v.x;
            sKV[(d4 + 1) * 68 + k] = v.y;
            sKV[(d4 + 2) * 68 + k] = v.z;
            sKV[(d4 + 3) * 68 + k] = v.w;
        }
        __syncthreads();

        float acc[4][4];
#pragma unroll
        for (int i = 0; i < 4; i++)
#pragma unroll
            for (int j = 0; j < 4; j++) acc[i][j] = 0.f;

#pragma unroll
        for (int d = 0; d < 64; d++) {
            float a[4], b[4];
            *(float4*)a = *(float4*)&sQt[d * 36 + ty * 4];
            *(float4*)b = *(float4*)&sKV[d * 68 + tx * 4];
#pragma unroll
            for (int i = 0; i < 4; i++)
#pragma unroll
                for (int j = 0; j < 4; j++)
                    acc[i][j] += a[i] * b[j];
        }
#pragma unroll
        for (int j = 0; j < 4; j++)
#pragma unroll
            for (int i = 0; i < 4; i++)
                sS[(kt * 64 + tx * 4 + j) * 36 + ty * 4 + i] = acc[i][j];
    }
    __syncthreads();

    {
        const int warp = tid >> 5, lane = tid & 31;
#pragma unroll
        for (int rr = 0; rr < 8; rr++) {
            const int r = warp * 8 + rr;
            float mx = -1e30f;
            for (int c = lane; c < 512; c += 32)
                mx = fmaxf(mx, sS[c * 36 + r]);
#pragma unroll
            for (int off = 16; off > 0; off >>= 1)
                mx = fmaxf(mx, __shfl_xor_sync(0xffffffffu, mx, off));
            float sum = 0.f;
            for (int c = lane; c < 512; c += 32) {
                const float e = __expf(sS[c * 36 + r] - mx);
                sS[c * 36 + r] = e;
                sum += e;
            }
#pragma unroll
            for (int off = 16; off > 0; off >>= 1)
                sum += __shfl_xor_sync(0xffffffffu, sum, off);
            if (lane == 0) sSum[r] = 1.0f / sum;
        }
    }
    __syncthreads();

    float o[4][4];
#pragma unroll
    for (int i = 0; i < 4; i++)
#pragma unroll
        for (int j = 0; j < 4; j++) o[i][j] = 0.f;

    for (int kt = 0; kt < 8; kt++) {
#pragma unroll
        for (int t = 0; t < 8; t++) {
            const int idx = t * 128 + tid;
            const int k = idx >> 4;
            const int d4 = (idx & 15) * 4;
            *(float4*)&sKV[k * 68 + d4] =
                *(const float4*)(Vg + (size_t)(kt * 64 + k) * HD + d4);
        }
        __syncthreads();
#pragma unroll
        for (int c = 0; c < 64; c++) {
            float a[4], b[4];
            *(float4*)a = *(float4*)&sS[(kt * 64 + c) * 36 + ty * 4];
            *(float4*)b = *(float4*)&sKV[c * 68 + tx * 4];
#pragma unroll
            for (int i = 0; i < 4; i++)
#pragma unroll
                for (int j = 0; j < 4; j++)
                    o[i][j] += a[i] * b[j];
        }
        __syncthreads();
    }

    const int wx = w >> 4, wy = (w >> 2) & 3, wz = w & 3;
#pragma unroll
    for (int i = 0; i < 4; i++) {
        const int r = ty * 4 + i;
        const int p = qt * 32 + r;
        const int ix = p >> 6, iy = (p >> 3) & 7, iz = p & 7;
        const int n = ((wx * 8 + ix) * 32 + (wy * 8 + iy)) * 32 + (wz * 8 + iz);
        const float s = sSum[r];
        float4 v;
        v.x = o[i][0] * s;
        v.y = o[i][1] * s;
        v.z = o[i][2] * s;
        v.w = o[i][3] * s;
        *(float4*)&g_hbuf[(size_t)n * CH + h * HD + tx * 4] = v;
    }
}

// ---------------------------------------------------------------------------
// kernel_launch
// inputs: 0:x 1:coords 2:Wqkv 3:bqkv 4:gamma_q 5:gamma_k 6:Wout 7:bout
// ---------------------------------------------------------------------------
extern "C" void kernel_launch(void* const* d_in, const int* in_sizes, int n_in,
                              void* d_out, int out_size)
{
    const float* x       = (const float*)d_in[0];
    const int*   coords  = (const int*)  d_in[1];
    const float* Wqkv    = (const float*)d_in[2];
    const float* bqkv    = (const float*)d_in[3];
    const float* gamma_q = (const float*)d_in[4];
    const float* gamma_k = (const float*)d_in[5];
    const float* Wout    = (const float*)d_in[6];
    const float* bout    = (const float*)d_in[7];
    float* out = (float*)d_out;

    float *qkv_p, *h_p;
    cudaGetSymbolAddress((void**)&qkv_p, g_qkv);
    cudaGetSymbolAddress((void**)&h_p,  g_hbuf);

    // 1) qkv = x @ Wqkv + bqkv           [32768,3072]  (TF32 tensor cores)
    sgemm_tf32<<<dim3(3 * CH / 128, NTOK / 128), 256>>>(
        x, Wqkv, bqkv, qkv_p, NTOK, 3 * CH, CH);

    // 2) rmsnorm + rope + window scatter
    qkv_post<<<NTOK, 512>>>(coords, gamma_q, gamma_k);

    // 3) windowed attention (fp32)
    const int smem_bytes = ATTN_SMEM_FLOATS * sizeof(float);
    cudaFuncSetAttribute(attn_win, cudaFuncAttributeMaxDynamicSharedMemorySize,
                         smem_bytes);
    attn_win<<<dim3(16, NH, NWIN), 128, smem_bytes>>>();

    // 4) out = h @ Wout + bout           [32768,1024]  (TF32 tensor cores)
    sgemm_tf32<<<dim3(CH / 128, NTOK / 128), 256>>>(
        h_p, Wout, bout, out, NTOK, CH, CH);
}

// round 5
// speedup vs baseline: 3.0344x; 1.7281x over previous
#include <cuda_runtime.h>
#include <math.h>
#include <stdint.h>

// ---------------------------------------------------------------------------
// Trellis2 windowed 3D attention.
//   x[32768,1024] -> qkv gemm (TF32 mma) -> rmsnorm+rope ->
//   windowed attn (TF32 mma, flash-style) -> out gemm (TF32 mma)
// ---------------------------------------------------------------------------

#define R3 32
#define NH 16
#define CH 1024
#define HD 64
#define NTOK (R3*R3*R3)      // 32768
#define NWIN 64              // (32/8)^3
#define WTOK 512             // 8^3

// ---- scratch (static device arrays; allocation-free at launch time) ----
__device__ float g_qkv[(size_t)NTOK * 3 * CH];            // 402 MB
__device__ float g_qw [(size_t)NWIN * NH * WTOK * HD];    // [w][h][p][d]
__device__ float g_kw [(size_t)NWIN * NH * WTOK * HD];
__device__ float g_vw [(size_t)NWIN * NH * WTOK * HD];
__device__ float g_hbuf[(size_t)NTOK * CH];               // attn out, token layout

// ---------------------------------------------------------------------------
// Common TF32 helpers
// ---------------------------------------------------------------------------
__device__ __forceinline__ unsigned f2tf32(float f) {
    unsigned u;
    asm("cvt.rna.tf32.f32 %0, %1;" : "=r"(u) : "f"(f));
    return u;
}

__device__ __forceinline__ void mma1688(float d[4], const unsigned a[4],
                                        const unsigned b[2]) {
    asm volatile(
        "mma.sync.aligned.m16n8k8.row.col.f32.tf32.tf32.f32 "
        "{%0,%1,%2,%3}, {%4,%5,%6,%7}, {%8,%9}, {%0,%1,%2,%3};"
        : "+f"(d[0]), "+f"(d[1]), "+f"(d[2]), "+f"(d[3])
        : "r"(a[0]), "r"(a[1]), "r"(a[2]), "r"(a[3]), "r"(b[0]), "r"(b[1]));
}

// ---------------------------------------------------------------------------
// TF32 tensor-core GEMM: C[M,N] = A[M,K] @ B[K,N] + bias[N]
// 128x128 block tile, BK=16, 256 threads (8 warps), warp tile 64x32.
// (unchanged from Round 4 — measured 125 TF/s effective)
// ---------------------------------------------------------------------------
__global__ __launch_bounds__(256) void sgemm_tf32(
    const float* __restrict__ A, const float* __restrict__ B,
    const float* __restrict__ bias, float* __restrict__ Cm,
    int M, int Nn, int K)
{
    __shared__ unsigned As[2][128][20];   // [buf][m][k] tf32 bits
    __shared__ unsigned Bs[2][16][136];   // [buf][k][n]

    const int tid  = threadIdx.x;
    const int warp = tid >> 5, lane = tid & 31;
    const int wm = warp >> 2;
    const int wn = warp & 3;
    const int grp = lane >> 2, tg = lane & 3;
    const int bx = blockIdx.x, by = blockIdx.y;

    const float* Ab = A + (size_t)by * 128 * K;
    const float* Bb = B + bx * 128;

    const int am  = tid >> 2;
    const int ac4 = (tid & 3) * 4;
    const int bk  = tid >> 5;
    const int bn4 = (lane) * 4;

    float d[4][4][4];
#pragma unroll
    for (int mt = 0; mt < 4; mt++)
#pragma unroll
        for (int nt = 0; nt < 4; nt++)
#pragma unroll
            for (int j = 0; j < 4; j++) d[mt][nt][j] = 0.f;

    {
        float4 a0 = *(const float4*)(Ab + (size_t)am        * K + ac4);
        float4 a1 = *(const float4*)(Ab + (size_t)(am + 64) * K + ac4);
        float4 b0 = *(const float4*)(Bb + (size_t)bk       * Nn + bn4);
        float4 b1 = *(const float4*)(Bb + (size_t)(bk + 8) * Nn + bn4);
        uint4 u;
        u.x = f2tf32(a0.x); u.y = f2tf32(a0.y); u.z = f2tf32(a0.z); u.w = f2tf32(a0.w);
        *(uint4*)&As[0][am][ac4] = u;
        u.x = f2tf32(a1.x); u.y = f2tf32(a1.y); u.z = f2tf32(a1.z); u.w = f2tf32(a1.w);
        *(uint4*)&As[0][am + 64][ac4] = u;
        u.x = f2tf32(b0.x); u.y = f2tf32(b0.y); u.z = f2tf32(b0.z); u.w = f2tf32(b0.w);
        *(uint4*)&Bs[0][bk][bn4] = u;
        u.x = f2tf32(b1.x); u.y = f2tf32(b1.y); u.z = f2tf32(b1.z); u.w = f2tf32(b1.w);
        *(uint4*)&Bs[0][bk + 8][bn4] = u;
    }
    __syncthreads();

    int buf = 0;
    for (int k0 = 16; k0 <= K; k0 += 16) {
        const bool has_next = (k0 < K);
        float4 ra0, ra1, rb0, rb1;
        if (has_next) {
            ra0 = *(const float4*)(Ab + (size_t)am        * K + k0 + ac4);
            ra1 = *(const float4*)(Ab + (size_t)(am + 64) * K + k0 + ac4);
            rb0 = *(const float4*)(Bb + (size_t)(k0 + bk    ) * Nn + bn4);
            rb1 = *(const float4*)(Bb + (size_t)(k0 + bk + 8) * Nn + bn4);
        }

#pragma unroll
        for (int ks = 0; ks < 2; ks++) {
            const int kb = ks * 8;
            unsigned a[4][4], b[4][2];
#pragma unroll
            for (int mt = 0; mt < 4; mt++) {
                const int r = wm * 64 + mt * 16 + grp;
                a[mt][0] = As[buf][r    ][kb + tg];
                a[mt][1] = As[buf][r + 8][kb + tg];
                a[mt][2] = As[buf][r    ][kb + tg + 4];
                a[mt][3] = As[buf][r + 8][kb + tg + 4];
            }
#pragma unroll
            for (int nt = 0; nt < 4; nt++) {
                const int c = wn * 32 + nt * 8 + grp;
                b[nt][0] = Bs[buf][kb + tg    ][c];
                b[nt][1] = Bs[buf][kb + tg + 4][c];
            }
#pragma unroll
            for (int mt = 0; mt < 4; mt++)
#pragma unroll
                for (int nt = 0; nt < 4; nt++)
                    mma1688(d[mt][nt], a[mt], b[nt]);
        }

        if (has_next) {
            const int nb = buf ^ 1;
            uint4 u;
            u.x = f2tf32(ra0.x); u.y = f2tf32(ra0.y); u.z = f2tf32(ra0.z); u.w = f2tf32(ra0.w);
            *(uint4*)&As[nb][am][ac4] = u;
            u.x = f2tf32(ra1.x); u.y = f2tf32(ra1.y); u.z = f2tf32(ra1.z); u.w = f2tf32(ra1.w);
            *(uint4*)&As[nb][am + 64][ac4] = u;
            u.x = f2tf32(rb0.x); u.y = f2tf32(rb0.y); u.z = f2tf32(rb0.z); u.w = f2tf32(rb0.w);
            *(uint4*)&Bs[nb][bk][bn4] = u;
            u.x = f2tf32(rb1.x); u.y = f2tf32(rb1.y); u.z = f2tf32(rb1.z); u.w = f2tf32(rb1.w);
            *(uint4*)&Bs[nb][bk + 8][bn4] = u;
            __syncthreads();
            buf = nb;
        }
    }

#pragma unroll
    for (int mt = 0; mt < 4; mt++) {
#pragma unroll
        for (int nt = 0; nt < 4; nt++) {
            const int col = bx * 128 + wn * 32 + nt * 8 + 2 * tg;
            const float bx0 = bias[col], bx1 = bias[col + 1];
            const size_t r0 = (size_t)by * 128 + wm * 64 + mt * 16 + grp;
            float2 v0, v1;
            v0.x = d[mt][nt][0] + bx0; v0.y = d[mt][nt][1] + bx1;
            v1.x = d[mt][nt][2] + bx0; v1.y = d[mt][nt][3] + bx1;
            *(float2*)(Cm + r0 * Nn + col)       = v0;
            *(float2*)(Cm + (r0 + 8) * Nn + col) = v1;
        }
    }
}

// ---------------------------------------------------------------------------
// Post-process: per (token, head) RMSNorm + RoPE on q,k; scatter q,k,v into
// windowed layout [w][h][p][d]. One block per token, 16 warps = 16 heads.
// ---------------------------------------------------------------------------
__global__ __launch_bounds__(512) void qkv_post(
    const int* __restrict__ coords,
    const float* __restrict__ gamma_q,
    const float* __restrict__ gamma_k)
{
    const int n = blockIdx.x;
    const int h = threadIdx.x >> 5;
    const int lane = threadIdx.x & 31;

    const int x = n >> 10, y = (n >> 5) & 31, z = n & 31;
    const int w = ((x >> 3) * 4 + (y >> 3)) * 4 + (z >> 3);
    const int p = ((x & 7) * 8 + (y & 7)) * 8 + (z & 7);

    float cosp = 1.f, sinp = 0.f;
    if (lane < 30) {
        const int c = lane / 10, f = lane % 10;
        const float freq = expf(-(float)f * 0.9210340371976183f);
        const float phase = (float)coords[n * 3 + c] * freq;
        sincosf(phase, &sinp, &cosp);
    }

    const size_t base  = (size_t)n * (3 * CH);
    const size_t wbase = (((size_t)w * NH + h) * WTOK + p) * HD;

    // Q
    {
        float2 t = *(const float2*)&g_qkv[base + h * HD + 2 * lane];
        float ss = t.x * t.x + t.y * t.y;
#pragma unroll
        for (int off = 16; off > 0; off >>= 1)
            ss += __shfl_xor_sync(0xffffffffu, ss, off);
        const float inv = 8.0f / fmaxf(sqrtf(ss), 1e-12f);
        float2 g = *(const float2*)&gamma_q[h * HD + 2 * lane];
        const float t0 = t.x * inv * g.x;
        const float t1 = t.y * inv * g.y;
        float2 o;
        o.x = t0 * cosp - t1 * sinp;
        o.y = t0 * sinp + t1 * cosp;
        *(float2*)&g_qw[wbase + 2 * lane] = o;
    }
    // K
    {
        float2 t = *(const float2*)&g_qkv[base + CH + h * HD + 2 * lane];
        float ss = t.x * t.x + t.y * t.y;
#pragma unroll
        for (int off = 16; off > 0; off >>= 1)
            ss += __shfl_xor_sync(0xffffffffu, ss, off);
        const float inv = 8.0f / fmaxf(sqrtf(ss), 1e-12f);
        float2 g = *(const float2*)&gamma_k[h * HD + 2 * lane];
        const float t0 = t.x * inv * g.x;
        const float t1 = t.y * inv * g.y;
        float2 o;
        o.x = t0 * cosp - t1 * sinp;
        o.y = t0 * sinp + t1 * cosp;
        *(float2*)&g_kw[wbase + 2 * lane] = o;
    }
    // V
    {
        float2 t = *(const float2*)&g_qkv[base + 2 * CH + h * HD + 2 * lane];
        *(float2*)&g_vw[wbase + 2 * lane] = t;
    }
}

// ---------------------------------------------------------------------------
// Windowed attention, TF32 tensor cores, flash-style online softmax.
// grid = (4 q-tiles, 16 heads, 64 windows), 256 threads (8 warps).
// Block: 128 q-rows x 512 keys, D=64. Warp w owns q-rows [16w, 16w+16).
// Loop over 8 chunks of 64 keys:
//   S = (Q/8).K^T  (m16n8k8 tf32)  -> online softmax in C-frag registers
//   P -> smem (tf32, warp-private rows) -> O += P.V (m16n8k8 tf32)
// smem (pitch 68 words, conflict-free for all frag patterns):
//   Qs[128][68], Ks[64][68], Vs[64][68], Ps[128][68]  ~102 KB
// ---------------------------------------------------------------------------
#define AP 68
#define ATTN_SMEM_WORDS (AP * (128 + 64 + 64 + 128))

__global__ __launch_bounds__(256) void attn_win_tc()
{
    extern __shared__ unsigned smu[];
    unsigned* Qs = smu;                  // [128][AP]
    unsigned* Ks = Qs + 128 * AP;        // [64][AP]
    unsigned* Vs = Ks + 64 * AP;         // [64][AP]
    unsigned* Ps = Vs + 64 * AP;         // [128][AP]

    const int tid  = threadIdx.x;
    const int warp = tid >> 5, lane = tid & 31;
    const int grp = lane >> 2, tg = lane & 3;
    const int qt = blockIdx.x, h = blockIdx.y, w = blockIdx.z;

    const float* Qg = g_qw + (((size_t)w * NH + h) * WTOK + qt * 128) * HD;
    const float* Kg = g_kw + ((size_t)w * NH + h) * WTOK * HD;
    const float* Vg = g_vw + ((size_t)w * NH + h) * WTOK * HD;

    // ---- load Q (tf32, pre-scaled by 1/sqrt(D)=0.125) ----
#pragma unroll
    for (int t = 0; t < 8; t++) {
        const int idx = t * 256 + tid;       // 0..2047
        const int r = idx >> 4;              // 0..127
        const int c4 = (idx & 15) * 4;
        float4 v = *(const float4*)(Qg + (size_t)r * HD + c4);
        uint4 u;
        u.x = f2tf32(v.x * 0.125f); u.y = f2tf32(v.y * 0.125f);
        u.z = f2tf32(v.z * 0.125f); u.w = f2tf32(v.w * 0.125f);
        *(uint4*)&Qs[r * AP + c4] = u;
    }

    const int rb = warp * 16;                // warp q-row base
    float m0 = -1e30f, m1 = -1e30f, l0 = 0.f, l1 = 0.f;
    float o[8][4];
#pragma unroll
    for (int nt = 0; nt < 8; nt++)
#pragma unroll
        for (int j = 0; j < 4; j++) o[nt][j] = 0.f;

    for (int kc = 0; kc < 8; kc++) {
        __syncthreads();  // Q stores visible (kc=0); prior chunk K/V reads done

        // ---- load K,V chunk [64 keys][64 d] as tf32 ----
#pragma unroll
        for (int t = 0; t < 4; t++) {
            const int idx = t * 256 + tid;   // 0..1023
            const int k = idx >> 4;
            const int c4 = (idx & 15) * 4;
            const size_t goff = (size_t)(kc * 64 + k) * HD + c4;
            float4 kv = *(const float4*)(Kg + goff);
            float4 vv = *(const float4*)(Vg + goff);
            uint4 u;
            u.x = f2tf32(kv.x); u.y = f2tf32(kv.y);
            u.z = f2tf32(kv.z); u.w = f2tf32(kv.w);
            *(uint4*)&Ks[k * AP + c4] = u;
            u.x = f2tf32(vv.x); u.y = f2tf32(vv.y);
            u.z = f2tf32(vv.z); u.w = f2tf32(vv.w);
            *(uint4*)&Vs[k * AP + c4] = u;
        }
        __syncthreads();

        // ---- S = Q.K^T  (16x64 per warp) ----
        float s[8][4];
#pragma unroll
        for (int nt = 0; nt < 8; nt++)
#pragma unroll
            for (int j = 0; j < 4; j++) s[nt][j] = 0.f;

#pragma unroll
        for (int ks = 0; ks < 8; ks++) {
            const int kb = ks * 8;
            unsigned a[4];
            a[0] = Qs[(rb + grp    ) * AP + kb + tg];
            a[1] = Qs[(rb + grp + 8) * AP + kb + tg];
            a[2] = Qs[(rb + grp    ) * AP + kb + tg + 4];
            a[3] = Qs[(rb + grp + 8) * AP + kb + tg + 4];
#pragma unroll
            for (int nt = 0; nt < 8; nt++) {
                unsigned b[2];
                b[0] = Ks[(nt * 8 + grp) * AP + kb + tg];
                b[1] = Ks[(nt * 8 + grp) * AP + kb + tg + 4];
                mma1688(s[nt], a, b);
            }
        }

        // ---- online softmax update (rows grp and grp+8) ----
        float cm0 = -1e30f, cm1 = -1e30f;
#pragma unroll
        for (int nt = 0; nt < 8; nt++) {
            cm0 = fmaxf(cm0, fmaxf(s[nt][0], s[nt][1]));
            cm1 = fmaxf(cm1, fmaxf(s[nt][2], s[nt][3]));
        }
        cm0 = fmaxf(cm0, __shfl_xor_sync(0xffffffffu, cm0, 1));
        cm0 = fmaxf(cm0, __shfl_xor_sync(0xffffffffu, cm0, 2));
        cm1 = fmaxf(cm1, __shfl_xor_sync(0xffffffffu, cm1, 1));
        cm1 = fmaxf(cm1, __shfl_xor_sync(0xffffffffu, cm1, 2));

        const float nm0 = fmaxf(m0, cm0);
        const float nm1 = fmaxf(m1, cm1);
        const float al0 = __expf(m0 - nm0);
        const float al1 = __expf(m1 - nm1);
        m0 = nm0; m1 = nm1;

        float cs0 = 0.f, cs1 = 0.f;
#pragma unroll
        for (int nt = 0; nt < 8; nt++) {
            const float p0 = __expf(s[nt][0] - nm0);
            const float p1 = __expf(s[nt][1] - nm0);
            const float p2 = __expf(s[nt][2] - nm1);
            const float p3 = __expf(s[nt][3] - nm1);
            cs0 += p0 + p1;
            cs1 += p2 + p3;
            uint2 u;
            u.x = f2tf32(p0); u.y = f2tf32(p1);
            *(uint2*)&Ps[(rb + grp    ) * AP + nt * 8 + 2 * tg] = u;
            u.x = f2tf32(p2); u.y = f2tf32(p3);
            *(uint2*)&Ps[(rb + grp + 8) * AP + nt * 8 + 2 * tg] = u;
        }
        cs0 += __shfl_xor_sync(0xffffffffu, cs0, 1);
        cs0 += __shfl_xor_sync(0xffffffffu, cs0, 2);
        cs1 += __shfl_xor_sync(0xffffffffu, cs1, 1);
        cs1 += __shfl_xor_sync(0xffffffffu, cs1, 2);
        l0 = l0 * al0 + cs0;
        l1 = l1 * al1 + cs1;

        // rescale running O
#pragma unroll
        for (int nt = 0; nt < 8; nt++) {
            o[nt][0] *= al0; o[nt][1] *= al0;
            o[nt][2] *= al1; o[nt][3] *= al1;
        }

        __syncwarp();  // Ps rows (warp-private) visible across lanes

        // ---- O += P.V ----
#pragma unroll
        for (int ks = 0; ks < 8; ks++) {
            const int kb = ks * 8;
            unsigned a[4];
            a[0] = Ps[(rb + grp    ) * AP + kb + tg];
            a[1] = Ps[(rb + grp + 8) * AP + kb + tg];
            a[2] = Ps[(rb + grp    ) * AP + kb + tg + 4];
            a[3] = Ps[(rb + grp + 8) * AP + kb + tg + 4];
#pragma unroll
            for (int nt = 0; nt < 8; nt++) {
                unsigned b[2];
                b[0] = Vs[(kb + tg    ) * AP + nt * 8 + grp];
                b[1] = Vs[(kb + tg + 4) * AP + nt * 8 + grp];
                mma1688(o[nt], a, b);
            }
        }
    }

    // ---- epilogue: normalize, write to natural token layout ----
    const float inv0 = 1.0f / l0;
    const float inv1 = 1.0f / l1;
    const int wx = w >> 4, wy = (w >> 2) & 3, wz = w & 3;

    const int p0r = qt * 128 + rb + grp;
    const int p1r = p0r + 8;
    const int n0 = ((wx * 8 + (p0r >> 6)) * 32 + (wy * 8 + ((p0r >> 3) & 7))) * 32
                 + (wz * 8 + (p0r & 7));
    const int n1 = ((wx * 8 + (p1r >> 6)) * 32 + (wy * 8 + ((p1r >> 3) & 7))) * 32
                 + (wz * 8 + (p1r & 7));

#pragma unroll
    for (int nt = 0; nt < 8; nt++) {
        const int col = h * HD + nt * 8 + 2 * tg;
        float2 v;
        v.x = o[nt][0] * inv0; v.y = o[nt][1] * inv0;
        *(float2*)&g_hbuf[(size_t)n0 * CH + col] = v;
        v.x = o[nt][2] * inv1; v.y = o[nt][3] * inv1;
        *(float2*)&g_hbuf[(size_t)n1 * CH + col] = v;
    }
}

// ---------------------------------------------------------------------------
// kernel_launch
// inputs: 0:x 1:coords 2:Wqkv 3:bqkv 4:gamma_q 5:gamma_k 6:Wout 7:bout
// ---------------------------------------------------------------------------
extern "C" void kernel_launch(void* const* d_in, const int* in_sizes, int n_in,
                              void* d_out, int out_size)
{
    const float* x       = (const float*)d_in[0];
    const int*   coords  = (const int*)  d_in[1];
    const float* Wqkv    = (const float*)d_in[2];
    const float* bqkv    = (const float*)d_in[3];
    const float* gamma_q = (const float*)d_in[4];
    const float* gamma_k = (const float*)d_in[5];
    const float* Wout    = (const float*)d_in[6];
    const float* bout    = (const float*)d_in[7];
    float* out = (float*)d_out;

    float *qkv_p, *h_p;
    cudaGetSymbolAddress((void**)&qkv_p, g_qkv);
    cudaGetSymbolAddress((void**)&h_p,  g_hbuf);

    // 1) qkv = x @ Wqkv + bqkv           [32768,3072]  (TF32 tensor cores)
    sgemm_tf32<<<dim3(3 * CH / 128, NTOK / 128), 256>>>(
        x, Wqkv, bqkv, qkv_p, NTOK, 3 * CH, CH);

    // 2) rmsnorm + rope + window scatter
    qkv_post<<<NTOK, 512>>>(coords, gamma_q, gamma_k);

    // 3) windowed attention (TF32 tensor cores, flash-style)
    const int smem_bytes = ATTN_SMEM_WORDS * sizeof(unsigned);
    cudaFuncSetAttribute(attn_win_tc,
                         cudaFuncAttributeMaxDynamicSharedMemorySize, smem_bytes);
    attn_win_tc<<<dim3(4, NH, NWIN), 256, smem_bytes>>>();

    // 4) out = h @ Wout + bout           [32768,1024]  (TF32 tensor cores)
    sgemm_tf32<<<dim3(CH / 128, NTOK / 128), 256>>>(
        h_p, Wout, bout, out, NTOK, CH, CH);
}